// round 9
// baseline (speedup 1.0000x reference)
#include <cuda_runtime.h>
#include <cstdint>

// CenterLoss collapses: mask is one-hot(labels) -> only B entries of the
// [B, C] distance matrix survive; clip() turns the other B*(C-1) zeros into
// the closed-form constant B*(C-1)*1e-12. No GEMM.
//
// Fully-integer, barrier-light reduction. Every level packs
//     bits [56,64): arrival count     bits [0,56): 2^22 fixed-point sum
// into one u64; integer adds are exactly associative -> bit-deterministic,
// and the op that completes the count RETURNS the finished total.
//   warp : redux.sync.add.u32 over 2^22-scaled lane partials (1 HW instr)
//   block: lane0 -> shared packed u64 atomic (no post-compute __syncthreads)
//   grid : completing warp -> single global packed u64 atomic
// The clip(1e-12, 1e12) never binds on real distances (~2*chi2(128), all
// >> 1e-12); the masked-zero clips are the exact closed-form constant.
// Ranges: warp sum < 2^31, block < 2^34, grand total < 2^41 << 2^56. Safe.

#define CL_BATCH 1024
#define CL_FEAT  128
#define CL_NUMC  100000

#define CL_THREADS 256
#define CL_BLOCKS  (CL_BATCH / 8)     // 128 blocks, 8 warps = 8 samples each

#define CL_LANE_SCALE 4194304.0f      // 2^22
#define CL_LANE_INV   (1.0 / 4194304.0)

#define CL_CNT_UNIT (1ULL << 56)
#define CL_SUM_MASK (CL_CNT_UNIT - 1ULL)

// Exact closed-form contribution of the B*(C-1) clipped zeros.
constexpr double CL_CLIP_CONST =
    (double)CL_BATCH * (double)(CL_NUMC - 1) * 1e-12;

__device__ unsigned long long g_cl_accum = 0ULL;

__device__ __forceinline__ unsigned int warp_sum_u32(unsigned int v)
{
    unsigned int r;
    asm volatile("redux.sync.add.u32 %0, %1, 0xffffffff;"
                 : "=r"(r) : "r"(v));
    return r;
}

__global__ void __launch_bounds__(CL_THREADS)
center_loss_fused(const float* __restrict__ x,
                  const int* __restrict__ labels,
                  const float* __restrict__ centers,
                  float* __restrict__ out)
{
    const int tid     = threadIdx.x;
    const int lane    = tid & 31;
    const int warpInB = tid >> 5;                      // 0..7
    const int sample  = blockIdx.x * 8 + warpInB;      // 0..1023

    __shared__ unsigned long long s_acc;
    if (tid == 0) s_acc = 0ULL;
    __syncthreads();   // only barrier: publish the zeroed accumulator
                       // (issued before any long-latency waits)

    // Broadcast label load (all lanes same address -> 1 request).
    const int lbl = labels[sample];

    // 128 floats per row = 32 lanes x float4.
    const float4 xv = reinterpret_cast<const float4*>(x + (size_t)sample * CL_FEAT)[lane];
    const float4 cv = reinterpret_cast<const float4*>(centers + (size_t)lbl * CL_FEAT)[lane];

    // ||x||^2 + ||c||^2 - 2 x.c, expanded like the reference.
    float p = 0.f;
    p += xv.x * xv.x + cv.x * cv.x - 2.f * xv.x * cv.x;
    p += xv.y * xv.y + cv.y * cv.y - 2.f * xv.y * cv.y;
    p += xv.z * xv.z + cv.z * cv.z - 2.f * xv.z * cv.z;
    p += xv.w * xv.w + cv.w * cv.w - 2.f * xv.w * cv.w;

    // 2^22 fixed point (rn; saturates tiny negative rounding to 0), then a
    // single-instruction exact warp sum. Result IS the quantized distance.
    const unsigned int usum = warp_sum_u32(__float2uint_rn(p * CL_LANE_SCALE));

    if (lane == 0) {
        // Block level: packed count|sum shared atomic, no barrier needed.
        const unsigned long long qW = (unsigned long long)usum + CL_CNT_UNIT;
        const unsigned long long nowB = atomicAdd(&s_acc, qW) + qW;

        if ((nowB >> 56) == 8ULL) {
            // Last warp of the block: nowB holds the exact block total.
            const unsigned long long qB = (nowB & CL_SUM_MASK) + CL_CNT_UNIT;
            const unsigned long long now = atomicAdd(&g_cl_accum, qB) + qB;

            if ((now >> 56) == (unsigned long long)CL_BLOCKS) {
                // Grid completer: exact integer grand total.
                double total = (double)(now & CL_SUM_MASK) * CL_LANE_INV
                             + CL_CLIP_CONST;
                out[0] = (float)(total / (double)CL_BATCH);
                g_cl_accum = 0ULL;    // reset for next graph replay
            }
        }
    }
}

extern "C" void kernel_launch(void* const* d_in, const int* in_sizes, int n_in,
                              void* d_out, int out_size)
{
    const float* x       = (const float*)d_in[0];
    const int*   labels  = (const int*)d_in[1];
    const float* centers = (const float*)d_in[2];
    float*       out     = (float*)d_out;

    center_loss_fused<<<CL_BLOCKS, CL_THREADS>>>(x, labels, centers, out);
}